// round 16
// baseline (speedup 1.0000x reference)
#include <cuda_runtime.h>
#include <cuda_bf16.h>
#include <mma.h>
#include <math.h>

using namespace nvcuda;

// ---------------------------------------------------------------------------
// ELMo embeddings. xW GEMM via bf16-split wmma (pre-converted operands);
// persistent LSTM recurrence with bf16-split wmma phase1 (Wr pre-split in
// SMEM), fp32 phase2, R9 barrier.
// ---------------------------------------------------------------------------

namespace {
constexpr int Bn = 8;     // batch
constexpr int Tn = 96;    // time
constexpr int En = 256;   // embed dim
constexpr int Hn = 2048;  // hidden
constexpr int Pn = 256;   // projection
constexpr int Gn = 8192;  // 4*H
constexpr int NBLK = 128; // persistent grid (2 dirs x 64)
constexpr int DBLK = 64;  // blocks per direction
}

// scratch (device globals; allocation-free)
__device__ float g_emb[Bn * Tn * En];
__device__ float g_y0[2][Bn * Tn * Pn];
__device__ float g_y1[2][Bn * Tn * Pn];
__device__ float g_xW[2][(size_t)Tn * Bn * Gn];  // x@Wk (no bias), step-major
__device__ float g_h[2][Bn * Pn];
__device__ float g_a[2][Bn * Hn];
__device__ float g_mean[3][Bn];
__device__ float g_var[3][Bn];

// bf16 split operands for the xW GEMM
__device__ __nv_bfloat16 g_wkh[4 * En * Gn];  // 16.8 MB
__device__ __nv_bfloat16 g_wkl[4 * En * Gn];
__device__ __nv_bfloat16 g_xh[2][Bn * Tn * En];
__device__ __nv_bfloat16 g_xl[2][Bn * Tn * En];

// barrier state (R9: per-dir atomic counter + flag; monotonic, replay-safe)
__device__ unsigned g_cnt[2];
__device__ unsigned g_flag[2];

// ---------------------------------------------------------------------------
__global__ void k_embed(const int* __restrict__ tok, const float* __restrict__ tab) {
    int i = blockIdx.x * 256 + threadIdx.x;  // B*T*E = 196608
    int bt = i >> 8;
    int e = i & 255;
    g_emb[i] = tab[(size_t)tok[bt] * En + e];
}

// split Wk into (hi, lo) bf16 once per launch
__global__ void k_cvt_w(const float* __restrict__ Wk) {
    int i = blockIdx.x * 1024 + threadIdx.x;  // 4*256*8192 = 8388608
    float v = Wk[i];
    __nv_bfloat16 hi = __float2bfloat16(v);
    g_wkh[i] = hi;
    g_wkl[i] = __float2bfloat16(v - __bfloat162float(hi));
}

// split layer input into (hi, lo) bf16; grid.y = dir slot
__global__ void k_cvt_x(int layer) {
    int slot = blockIdx.y;
    int i = blockIdx.x * 1024 + threadIdx.x;  // 768*256 = 196608
    float v = (layer == 0) ? g_emb[i] : g_y0[slot][i];
    __nv_bfloat16 hi = __float2bfloat16(v);
    g_xh[slot][i] = hi;
    g_xl[slot][i] = __float2bfloat16(v - __bfloat162float(hi));
}

// ---------------------------------------------------------------------------
// xW GEMM on bf16 tensor cores (unchanged from R15, measured best).
// ---------------------------------------------------------------------------
__global__ void __launch_bounds__(256, 2)
k_xw_bf16(int layer) {
    const int d = blockIdx.z;
    const int widx = d * 2 + layer;
    const __nv_bfloat16* __restrict__ XH = g_xh[d];
    const __nv_bfloat16* __restrict__ XL = g_xl[d];
    const __nv_bfloat16* __restrict__ WH = g_wkh + (size_t)widx * En * Gn;
    const __nv_bfloat16* __restrict__ WL = g_wkl + (size_t)widx * En * Gn;
    float* __restrict__ out = g_xW[d];
    const int n0 = blockIdx.x * 128;
    const int m0 = blockIdx.y * 128;
    const bool rev = (d == 1);
    const int tid = threadIdx.x;

    __shared__ __nv_bfloat16 AsH[128][40];
    __shared__ __nv_bfloat16 AsL[128][40];
    __shared__ __nv_bfloat16 BsH[32][136];
    __shared__ __nv_bfloat16 BsL[32][136];

    const int wid = tid >> 5;
    const int wr = wid >> 2;
    const int wc = wid & 3;

    wmma::fragment<wmma::accumulator, 16, 16, 16, float> acc[4][2];
#pragma unroll
    for (int i = 0; i < 4; ++i)
#pragma unroll
        for (int j = 0; j < 2; ++j) wmma::fill_fragment(acc[i][j], 0.f);

    const int ml = tid >> 1;
    const int kl = (tid & 1) * 16;
    const int m = m0 + ml;
    const int sA = m >> 3, bA = m & 7;
    const int tA = rev ? (Tn - 1 - sA) : sA;
    const __nv_bfloat16* xrowH = XH + (size_t)(bA * Tn + tA) * En;
    const __nv_bfloat16* xrowL = XL + (size_t)(bA * Tn + tA) * En;

    const int kb = tid >> 3;
    const int nb = (tid & 7) * 16;

    for (int k0 = 0; k0 < En; k0 += 32) {
        {
            *(uint4*)&AsH[ml][kl]     = *(const uint4*)(xrowH + k0 + kl);
            *(uint4*)&AsH[ml][kl + 8] = *(const uint4*)(xrowH + k0 + kl + 8);
            *(uint4*)&AsL[ml][kl]     = *(const uint4*)(xrowL + k0 + kl);
            *(uint4*)&AsL[ml][kl + 8] = *(const uint4*)(xrowL + k0 + kl + 8);
            const __nv_bfloat16* wH = WH + (size_t)(k0 + kb) * Gn + n0 + nb;
            const __nv_bfloat16* wL = WL + (size_t)(k0 + kb) * Gn + n0 + nb;
            *(uint4*)&BsH[kb][nb]     = *(const uint4*)(wH);
            *(uint4*)&BsH[kb][nb + 8] = *(const uint4*)(wH + 8);
            *(uint4*)&BsL[kb][nb]     = *(const uint4*)(wL);
            *(uint4*)&BsL[kb][nb + 8] = *(const uint4*)(wL + 8);
        }
        __syncthreads();
#pragma unroll
        for (int kk = 0; kk < 32; kk += 16) {
            wmma::fragment<wmma::matrix_b, 16, 16, 16, __nv_bfloat16,
                           wmma::row_major> bh[2], bl[2];
#pragma unroll
            for (int j = 0; j < 2; ++j) {
                wmma::load_matrix_sync(bh[j], &BsH[kk][wc * 32 + j * 16], 136);
                wmma::load_matrix_sync(bl[j], &BsL[kk][wc * 32 + j * 16], 136);
            }
#pragma unroll
            for (int i = 0; i < 4; ++i) {
                wmma::fragment<wmma::matrix_a, 16, 16, 16, __nv_bfloat16,
                               wmma::row_major> ah, al;
                wmma::load_matrix_sync(ah, &AsH[wr * 64 + i * 16][kk], 40);
                wmma::load_matrix_sync(al, &AsL[wr * 64 + i * 16][kk], 40);
#pragma unroll
                for (int j = 0; j < 2; ++j) {
                    wmma::mma_sync(acc[i][j], ah, bh[j], acc[i][j]);
                    wmma::mma_sync(acc[i][j], ah, bl[j], acc[i][j]);
                    wmma::mma_sync(acc[i][j], al, bh[j], acc[i][j]);
                }
            }
        }
        __syncthreads();
    }
#pragma unroll
    for (int i = 0; i < 4; ++i)
#pragma unroll
        for (int j = 0; j < 2; ++j)
            wmma::store_matrix_sync(
                out + (size_t)(m0 + wr * 64 + i * 16) * Gn + n0 + wc * 32 + j * 16,
                acc[i][j], Gn, wmma::mem_row_major);
}

// ---------------------------------------------------------------------------
// Persistent LSTM recurrence. 128 blocks x 512 threads, 1 block/SM.
// Phase1 (z = h @ Wr) on bf16 tensor cores: Wr slice pre-split hi/lo in SMEM
// (same 128 KB as fp32), h split per step into a padded 16x256 A tile.
// ---------------------------------------------------------------------------
__device__ __forceinline__ float fsig(float x) {
    return __fdividef(1.f, 1.f + __expf(-x));
}
__device__ __forceinline__ float ftanh(float x) {
    return __fdividef(2.f, 1.f + __expf(-2.f * x)) - 1.f;
}

// R9 barrier: atomic arrive, thread-0 spins on one flag. (Measured best.)
__device__ __forceinline__ void dir_barrier(int d, unsigned target, int tid) {
    __syncthreads();
    if (tid == 0) {
        __threadfence();
        unsigned old = atomicAdd(&g_cnt[d], 1u);
        if (old + 1u == target)
            *((volatile unsigned*)&g_flag[d]) = target;
        while ((int)(*((volatile unsigned*)&g_flag[d]) - target) < 0) {}
    }
    __syncthreads();
    __threadfence();
}

// SMEM byte offsets (all 256-aligned)
namespace {
constexpr int OB_WRH = 0;        // bf16 [256][136]  69632 B
constexpr int OB_WRL = 69632;    // bf16 [256][136]  69632 B
constexpr int OB_AH  = 139264;   // bf16 [16][264]    8448 B
constexpr int OB_AL  = 147712;   // bf16 [16][264]    8448 B
constexpr int OB_WP  = 156160;   // f32  [4][2048]   32768 B
constexpr int OB_ZP  = 188928;   // f32  [2][16][128] 16384 B
constexpr int OB_Z   = 205312;   // f32  [8][128]     4096 B
constexpr int OB_C   = 209408;   // f32  [8][32]      1024 B
constexpr int OB_RD  = 210432;   // f32  [8][2][4]     256 B
constexpr int OB_B   = 210688;   // f32  [128]         512 B
constexpr int SM_BYTES = 211200;
}

__global__ void __launch_bounds__(512, 1)
k_recur(const float* __restrict__ Wr, const float* __restrict__ Wp,
        const float* __restrict__ bias, const float* __restrict__ mask,
        int layer) {
    extern __shared__ __align__(256) char smx[];
    __nv_bfloat16* WrH = (__nv_bfloat16*)(smx + OB_WRH);
    __nv_bfloat16* WrL = (__nv_bfloat16*)(smx + OB_WRL);
    __nv_bfloat16* AH  = (__nv_bfloat16*)(smx + OB_AH);
    __nv_bfloat16* AL  = (__nv_bfloat16*)(smx + OB_AL);
    float* Wp_sm = (float*)(smx + OB_WP);
    float* zpart = (float*)(smx + OB_ZP);
    float* z_sm  = (float*)(smx + OB_Z);
    float* c_sm  = (float*)(smx + OB_C);
    float* red   = (float*)(smx + OB_RD);
    float* b_sm  = (float*)(smx + OB_B);

    const int tid = threadIdx.x;
    const int bx = blockIdx.x;
    const int d = bx >> 6;
    const int q = bx & 63;
    const int U0 = q * 32;
    const int P0 = q * 4;
    const int widx = d * 2 + layer;

    // ---- preload weights (Wr split to bf16 hi/lo), bias; zero A tile ----
    {
        const float* Wg = Wr + (size_t)widx * Pn * Gn;
        for (int i = tid; i < 256 * 128; i += 512) {
            int k = i >> 7, lc = i & 127;
            int gate = lc >> 5, u = lc & 31;
            float v = __ldg(&Wg[(size_t)k * Gn + gate * Hn + U0 + u]);
            __nv_bfloat16 hi = __float2bfloat16(v);
            WrH[k * 136 + lc] = hi;
            WrL[k * 136 + lc] = __float2bfloat16(v - __bfloat162float(hi));
        }
        const float* Wpg = Wp + (size_t)widx * Hn * Pn;
        for (int k = tid; k < Hn; k += 512) {
            float4 v = __ldg((const float4*)&Wpg[(size_t)k * Pn + P0]);
            Wp_sm[k] = v.x;
            Wp_sm[2048 + k] = v.y;
            Wp_sm[4096 + k] = v.z;
            Wp_sm[6144 + k] = v.w;
        }
        if (tid < 128) {
            int gate = tid >> 5, u = tid & 31;
            b_sm[tid] = __ldg(&bias[(size_t)widx * Gn + gate * Hn + U0 + u]);
        }
        for (int i = tid; i < 16 * 264; i += 512) {
            AH[i] = __float2bfloat16(0.f);
            AL[i] = __float2bfloat16(0.f);
        }
    }
    if (tid < 256) c_sm[tid] = 0.f;

    const unsigned base = *((volatile unsigned*)&g_flag[d]);
    unsigned target = base;
    float h_own = 0.f;
    float* __restrict__ yb = (layer == 0) ? g_y0[d] : g_y1[d];
    float* __restrict__ hg = g_h[d];
    float* __restrict__ ag = g_a[d];
    const float* __restrict__ xWd = g_xW[d];
    __syncthreads();

    // role indices
    const int w = tid >> 5;           // warp id
    const int lane = tid & 31;
    const int half = w & 1;           // phase1: k half / phase2: k half
    const int nt = w >> 1;            // phase1: n-tile (0..7)
    const int rb = tid >> 6;          // reduce: batch
    const int l2 = (tid & 63) * 2;    // reduce: 2 cols
    const int rgate = l2 >> 5, ru = l2 & 31;
    const int pb = w >> 1;            // phase2 batch

    for (int s = 0; s < Tn; ++s) {
        const int t = d ? (Tn - 1 - s) : s;

        // prefetch xW for the reduce stage (hide DRAM latency behind phase1)
        float2 xwv = __ldcg((const float2*)&xWd[((size_t)s * Bn + rb) * Gn +
                                                rgate * Hn + U0 + ru]);

        // ---- stage h split into A tile rows 0..7 (rows 8..15 stay zero) ----
        if (s > 0) {
#pragma unroll
            for (int i = tid; i < Bn * Pn; i += 512) {
                int b = i >> 8, p = i & 255;
                float v = __ldcg(&hg[i]);
                __nv_bfloat16 hi = __float2bfloat16(v);
                AH[b * 264 + p] = hi;
                AL[b * 264 + p] = __float2bfloat16(v - __bfloat162float(hi));
            }
        }
        __syncthreads();

        // ---- phase 1: z partials = h @ Wr via bf16 wmma (16 warps:
        //      2 k-halves x 8 n-tiles; 3-term split) ----
        {
            wmma::fragment<wmma::accumulator, 16, 16, 16, float> acc;
            wmma::fill_fragment(acc, 0.f);
#pragma unroll
            for (int j = 0; j < 8; ++j) {
                const int kt = half * 8 + j;
                wmma::fragment<wmma::matrix_a, 16, 16, 16, __nv_bfloat16,
                               wmma::row_major> ah, al;
                wmma::fragment<wmma::matrix_b, 16, 16, 16, __nv_bfloat16,
                               wmma::row_major> bh, bl;
                wmma::load_matrix_sync(ah, AH + kt * 16, 264);
                wmma::load_matrix_sync(al, AL + kt * 16, 264);
                wmma::load_matrix_sync(bh, WrH + (kt * 16) * 136 + nt * 16, 136);
                wmma::load_matrix_sync(bl, WrL + (kt * 16) * 136 + nt * 16, 136);
                wmma::mma_sync(acc, ah, bh, acc);
                wmma::mma_sync(acc, ah, bl, acc);
                wmma::mma_sync(acc, al, bh, acc);
            }
            wmma::store_matrix_sync(zpart + half * 2048 + nt * 16, acc, 128,
                                    wmma::mem_row_major);
        }
        __syncthreads();

        // ---- reduce 2 k-halves + add xW + bias ----
        {
            float z0 = xwv.x + b_sm[l2];
            float z1 = xwv.y + b_sm[l2 + 1];
            float2 p0 = *(const float2*)(zpart + rb * 128 + l2);
            float2 p1 = *(const float2*)(zpart + 2048 + rb * 128 + l2);
            *(float2*)(z_sm + rb * 128 + l2) =
                make_float2(z0 + p0.x + p1.x, z1 + p0.y + p1.y);
        }
        __syncthreads();

        // ---- gates / cell / a ----
        if (tid < 256) {
            const int b2 = tid >> 5, u = tid & 31;
            float zi = z_sm[b2 * 128 + u];
            float zf = z_sm[b2 * 128 + 32 + u];
            float zg = z_sm[b2 * 128 + 64 + u];
            float zo = z_sm[b2 * 128 + 96 + u];
            float ig = fsig(zi), fg = fsig(zf), gg = ftanh(zg), og = fsig(zo);
            float cold = c_sm[tid];
            float cn = fminf(3.f, fmaxf(-3.f, fg * cold + ig * gg));
            float mt = __ldg(&mask[b2 * Tn + t]);
            c_sm[tid] = (mt > 0.f) ? cn : cold;
            __stcg(&ag[b2 * Hn + U0 + u], og * ftanh(cn));
        }
        target += DBLK;
        dir_barrier(d, target, tid);

        // ---- phase 2: h cols P0..P0+3 = clip(a @ Wp) ----
        {
            const float4* av4 = (const float4*)(ag + pb * Hn + half * 1024);
            float q0 = 0.f, q1 = 0.f, q2 = 0.f, q3 = 0.f;
#pragma unroll
            for (int j = 0; j < 8; ++j) {
                float4 av = __ldcg(av4 + lane + j * 32);
                const int kk = half * 1024 + (lane + j * 32) * 4;
                float4 wa = *(const float4*)&Wp_sm[kk];
                float4 wb = *(const float4*)&Wp_sm[2048 + kk];
                float4 wc = *(const float4*)&Wp_sm[4096 + kk];
                float4 wd = *(const float4*)&Wp_sm[6144 + kk];
                q0 += av.x * wa.x + av.y * wa.y + av.z * wa.z + av.w * wa.w;
                q1 += av.x * wb.x + av.y * wb.y + av.z * wb.z + av.w * wb.w;
                q2 += av.x * wc.x + av.y * wc.y + av.z * wc.z + av.w * wc.w;
                q3 += av.x * wd.x + av.y * wd.y + av.z * wd.z + av.w * wd.w;
            }
#pragma unroll
            for (int off = 16; off; off >>= 1) {
                q0 += __shfl_xor_sync(0xffffffffu, q0, off);
                q1 += __shfl_xor_sync(0xffffffffu, q1, off);
                q2 += __shfl_xor_sync(0xffffffffu, q2, off);
                q3 += __shfl_xor_sync(0xffffffffu, q3, off);
            }
            if (lane == 0)
                *(float4*)(red + (pb * 2 + half) * 4) = make_float4(q0, q1, q2, q3);
        }
        __syncthreads();
        if (tid < 32) {
            const int bb = tid >> 2, pp = tid & 3;
            float hv = red[(bb * 2) * 4 + pp] + red[(bb * 2 + 1) * 4 + pp];
            hv = fminf(3.f, fmaxf(-3.f, hv));
            float mt = __ldg(&mask[bb * Tn + t]);
            float hn = (mt > 0.f) ? hv : h_own;
            h_own = hn;
            __stcg(&hg[bb * Pn + P0 + pp], hn);
            yb[((size_t)bb * Tn + t) * Pn + P0 + pp] = hn;
        }
        target += DBLK;
        dir_barrier(d, target, tid);
    }
}

// ---------------------------------------------------------------------------
// Epilogue (unchanged)
// ---------------------------------------------------------------------------
__device__ __forceinline__ float layer_val(int l, int b, int t, int ch) {
    if (l == 0) return g_emb[(size_t)(b * Tn + t) * En + (ch & 255)];
    const int dd = ch >> 8;
    const size_t idx = (size_t)(b * Tn + t) * Pn + (ch & 255);
    float v = g_y0[dd][idx];
    if (l == 2) v += g_y1[dd][idx];
    return v;
}

__global__ void k_stats(const float* __restrict__ mask) {
    const int b = blockIdx.x;
    const int l = blockIdx.y;
    __shared__ float red[256];
    const int tid = threadIdx.x;

    float nm = 0.f;
    for (int t = tid; t < Tn; t += 256) nm += mask[b * Tn + t];
    red[tid] = nm;
    __syncthreads();
    for (int st = 128; st > 0; st >>= 1) {
        if (tid < st) red[tid] += red[tid + st];
        __syncthreads();
    }
    const float num = red[0];
    __syncthreads();

    float smv = 0.f;
    for (int i = tid; i < Tn * 512; i += 256) {
        int t = i >> 9, ch = i & 511;
        smv += layer_val(l, b, t, ch) * mask[b * Tn + t];
    }
    red[tid] = smv;
    __syncthreads();
    for (int st = 128; st > 0; st >>= 1) {
        if (tid < st) red[tid] += red[tid + st];
        __syncthreads();
    }
    const float mean = red[0] / num;
    __syncthreads();

    float vs = 0.f;
    for (int i = tid; i < Tn * 512; i += 256) {
        int t = i >> 9, ch = i & 511;
        float m = mask[b * Tn + t];
        float dd = (layer_val(l, b, t, ch) * m - mean) * m;
        vs += dd * dd;
    }
    red[tid] = vs;
    __syncthreads();
    for (int st = 128; st > 0; st >>= 1) {
        if (tid < st) red[tid] += red[tid + st];
        __syncthreads();
    }
    if (tid == 0) {
        g_mean[l][b] = mean;
        g_var[l][b] = red[0] / num;
    }
}

__global__ void k_final(const float* __restrict__ elmo_w, const float* __restrict__ gamma,
                        float* __restrict__ out) {
    const int i = blockIdx.x * 256 + threadIdx.x;
    const int ch = i & 511;
    const int bt = i >> 9;
    const int b = bt / Tn;
    const int t = bt - b * Tn;
    float w0 = elmo_w[0], w1 = elmo_w[1], w2 = elmo_w[2];
    float mx = fmaxf(w0, fmaxf(w1, w2));
    float e0 = expf(w0 - mx), e1 = expf(w1 - mx), e2 = expf(w2 - mx);
    float inv = 1.f / (e0 + e1 + e2);
    float gm = gamma[0];
    float r = 0.f;
    r += e0 * inv * (layer_val(0, b, t, ch) - g_mean[0][b]) / sqrtf(g_var[0][b] + 1e-12f);
    r += e1 * inv * (layer_val(1, b, t, ch) - g_mean[1][b]) / sqrtf(g_var[1][b] + 1e-12f);
    r += e2 * inv * (layer_val(2, b, t, ch) - g_mean[2][b]) / sqrtf(g_var[2][b] + 1e-12f);
    out[i] = gm * r;
}

// ---------------------------------------------------------------------------
extern "C" void kernel_launch(void* const* d_in, const int* in_sizes, int n_in,
                              void* d_out, int out_size) {
    (void)in_sizes; (void)n_in; (void)out_size;
    const int*   tokens = (const int*)d_in[0];
    const float* mask   = (const float*)d_in[1];
    const float* table  = (const float*)d_in[2];
    const float* Wk     = (const float*)d_in[3];
    const float* Wr     = (const float*)d_in[4];
    const float* bias   = (const float*)d_in[5];
    const float* Wp     = (const float*)d_in[6];
    const float* elmo_w = (const float*)d_in[7];
    const float* gamma  = (const float*)d_in[8];
    float* out = (float*)d_out;

    cudaFuncSetAttribute(k_recur, cudaFuncAttributeMaxDynamicSharedMemorySize,
                         SM_BYTES);

    k_embed<<<768, 256>>>(tokens, table);
    k_cvt_w<<<8192, 1024>>>(Wk);
    for (int layer = 0; layer < 2; ++layer) {
        k_cvt_x<<<dim3(192, 2), 1024>>>(layer);
        k_xw_bf16<<<dim3(Gn / 128, (Tn * Bn) / 128, 2), 256>>>(layer);
        k_recur<<<NBLK, 512, SM_BYTES>>>(Wr, Wp, bias, mask, layer);
    }
    k_stats<<<dim3(8, 3), 256>>>(mask);
    k_final<<<1536, 256>>>(elmo_w, gamma, out);
}

// round 17
// speedup vs baseline: 1.0578x; 1.0578x over previous
#include <cuda_runtime.h>
#include <cuda_bf16.h>
#include <mma.h>
#include <math.h>

using namespace nvcuda;

// ---------------------------------------------------------------------------
// ELMo embeddings. bf16-split wmma xW GEMM (R15, measured 100us/launch) +
// R9-exact persistent fp32 LSTM recurrence (measured 6.6us/step) with bias
// folded into the reduce stage. cvt_x launches eliminated (splits produced
// by k_embed / k_recur).
// ---------------------------------------------------------------------------

namespace {
constexpr int Bn = 8;     // batch
constexpr int Tn = 96;    // time
constexpr int En = 256;   // embed dim
constexpr int Hn = 2048;  // hidden
constexpr int Pn = 256;   // projection
constexpr int Gn = 8192;  // 4*H
constexpr int NBLK = 128; // persistent grid (2 dirs x 64)
constexpr int DBLK = 64;  // blocks per direction
}

// scratch (device globals; allocation-free)
__device__ float g_emb[Bn * Tn * En];
__device__ float g_y0[2][Bn * Tn * Pn];
__device__ float g_y1[2][Bn * Tn * Pn];
__device__ float g_xW[2][(size_t)Tn * Bn * Gn];  // x@Wk (no bias), step-major
__device__ float g_h[2][Bn * Pn];
__device__ float g_a[2][Bn * Hn];
__device__ float g_mean[3][Bn];
__device__ float g_var[3][Bn];

// bf16 split operands for the xW GEMM
__device__ __nv_bfloat16 g_wkh[4 * En * Gn];  // 16.8 MB
__device__ __nv_bfloat16 g_wkl[4 * En * Gn];
__device__ __nv_bfloat16 g_xh[2][Bn * Tn * En];
__device__ __nv_bfloat16 g_xl[2][Bn * Tn * En];

// barrier state (R9: per-dir atomic counter + flag; monotonic, replay-safe)
__device__ unsigned g_cnt[2];
__device__ unsigned g_flag[2];

// ---------------------------------------------------------------------------
// embed + emit layer-0 bf16 splits for both dir slots
__global__ void k_embed(const int* __restrict__ tok, const float* __restrict__ tab) {
    int i = blockIdx.x * 256 + threadIdx.x;  // B*T*E = 196608
    int bt = i >> 8;
    int e = i & 255;
    float v = tab[(size_t)tok[bt] * En + e];
    g_emb[i] = v;
    __nv_bfloat16 hi = __float2bfloat16(v);
    __nv_bfloat16 lo = __float2bfloat16(v - __bfloat162float(hi));
    g_xh[0][i] = hi;
    g_xl[0][i] = lo;
    g_xh[1][i] = hi;
    g_xl[1][i] = lo;
}

// split Wk into (hi, lo) bf16 once per launch
__global__ void k_cvt_w(const float* __restrict__ Wk) {
    int i = blockIdx.x * 1024 + threadIdx.x;  // 4*256*8192 = 8388608
    float v = Wk[i];
    __nv_bfloat16 hi = __float2bfloat16(v);
    g_wkh[i] = hi;
    g_wkl[i] = __float2bfloat16(v - __bfloat162float(hi));
}

// ---------------------------------------------------------------------------
// xW GEMM on bf16 tensor cores (R15 version, measured best: 100us/launch).
// ---------------------------------------------------------------------------
__global__ void __launch_bounds__(256, 2)
k_xw_bf16(int layer) {
    const int d = blockIdx.z;
    const int widx = d * 2 + layer;
    const __nv_bfloat16* __restrict__ XH = g_xh[d];
    const __nv_bfloat16* __restrict__ XL = g_xl[d];
    const __nv_bfloat16* __restrict__ WH = g_wkh + (size_t)widx * En * Gn;
    const __nv_bfloat16* __restrict__ WL = g_wkl + (size_t)widx * En * Gn;
    float* __restrict__ out = g_xW[d];
    const int n0 = blockIdx.x * 128;
    const int m0 = blockIdx.y * 128;
    const bool rev = (d == 1);
    const int tid = threadIdx.x;

    __shared__ __nv_bfloat16 AsH[128][40];
    __shared__ __nv_bfloat16 AsL[128][40];
    __shared__ __nv_bfloat16 BsH[32][136];
    __shared__ __nv_bfloat16 BsL[32][136];

    const int wid = tid >> 5;
    const int wr = wid >> 2;
    const int wc = wid & 3;

    wmma::fragment<wmma::accumulator, 16, 16, 16, float> acc[4][2];
#pragma unroll
    for (int i = 0; i < 4; ++i)
#pragma unroll
        for (int j = 0; j < 2; ++j) wmma::fill_fragment(acc[i][j], 0.f);

    const int ml = tid >> 1;
    const int kl = (tid & 1) * 16;
    const int m = m0 + ml;
    const int sA = m >> 3, bA = m & 7;
    const int tA = rev ? (Tn - 1 - sA) : sA;
    const __nv_bfloat16* xrowH = XH + (size_t)(bA * Tn + tA) * En;
    const __nv_bfloat16* xrowL = XL + (size_t)(bA * Tn + tA) * En;

    const int kb = tid >> 3;
    const int nb = (tid & 7) * 16;

    for (int k0 = 0; k0 < En; k0 += 32) {
        {
            *(uint4*)&AsH[ml][kl]     = *(const uint4*)(xrowH + k0 + kl);
            *(uint4*)&AsH[ml][kl + 8] = *(const uint4*)(xrowH + k0 + kl + 8);
            *(uint4*)&AsL[ml][kl]     = *(const uint4*)(xrowL + k0 + kl);
            *(uint4*)&AsL[ml][kl + 8] = *(const uint4*)(xrowL + k0 + kl + 8);
            const __nv_bfloat16* wH = WH + (size_t)(k0 + kb) * Gn + n0 + nb;
            const __nv_bfloat16* wL = WL + (size_t)(k0 + kb) * Gn + n0 + nb;
            *(uint4*)&BsH[kb][nb]     = *(const uint4*)(wH);
            *(uint4*)&BsH[kb][nb + 8] = *(const uint4*)(wH + 8);
            *(uint4*)&BsL[kb][nb]     = *(const uint4*)(wL);
            *(uint4*)&BsL[kb][nb + 8] = *(const uint4*)(wL + 8);
        }
        __syncthreads();
#pragma unroll
        for (int kk = 0; kk < 32; kk += 16) {
            wmma::fragment<wmma::matrix_b, 16, 16, 16, __nv_bfloat16,
                           wmma::row_major> bh[2], bl[2];
#pragma unroll
            for (int j = 0; j < 2; ++j) {
                wmma::load_matrix_sync(bh[j], &BsH[kk][wc * 32 + j * 16], 136);
                wmma::load_matrix_sync(bl[j], &BsL[kk][wc * 32 + j * 16], 136);
            }
#pragma unroll
            for (int i = 0; i < 4; ++i) {
                wmma::fragment<wmma::matrix_a, 16, 16, 16, __nv_bfloat16,
                               wmma::row_major> ah, al;
                wmma::load_matrix_sync(ah, &AsH[wr * 64 + i * 16][kk], 40);
                wmma::load_matrix_sync(al, &AsL[wr * 64 + i * 16][kk], 40);
#pragma unroll
                for (int j = 0; j < 2; ++j) {
                    wmma::mma_sync(acc[i][j], ah, bh[j], acc[i][j]);
                    wmma::mma_sync(acc[i][j], ah, bl[j], acc[i][j]);
                    wmma::mma_sync(acc[i][j], al, bh[j], acc[i][j]);
                }
            }
        }
        __syncthreads();
    }
#pragma unroll
    for (int i = 0; i < 4; ++i)
#pragma unroll
        for (int j = 0; j < 2; ++j)
            wmma::store_matrix_sync(
                out + (size_t)(m0 + wr * 64 + i * 16) * Gn + n0 + wc * 32 + j * 16,
                acc[i][j], Gn, wmma::mem_row_major);
}

// ---------------------------------------------------------------------------
// Persistent LSTM recurrence — R9 version exactly (8-warp phase1, fp32,
// atomic+flag barrier), + bias in reduce + y-split emission for layer 1.
// 128 blocks x 512 threads. Block bx: dir d = bx>>6, slice q = bx&63.
// ---------------------------------------------------------------------------
__device__ __forceinline__ float fsig(float x) {
    return __fdividef(1.f, 1.f + __expf(-x));
}
__device__ __forceinline__ float ftanh(float x) {
    return __fdividef(2.f, 1.f + __expf(-2.f * x)) - 1.f;
}

__device__ __forceinline__ void dir_barrier(int d, unsigned target, int tid) {
    __syncthreads();
    if (tid == 0) {
        __threadfence();
        unsigned old = atomicAdd(&g_cnt[d], 1u);
        if (old + 1u == target)
            *((volatile unsigned*)&g_flag[d]) = target;
        while ((int)(*((volatile unsigned*)&g_flag[d]) - target) < 0) {}
    }
    __syncthreads();
    __threadfence();
}

// SMEM float offsets
namespace {
constexpr int OF_WR = 0;       // [256][128] (k*128+lc), lc = gate*32+u
constexpr int OF_WP = 32768;   // [4][2048]  (p*2048+k)
constexpr int OF_HT = 40960;   // [256][8]   (p*8+b) transposed h
constexpr int OF_ZP = 43008;   // [8][8][128] (kc*1024 + b*128 + lc)
constexpr int OF_Z  = 51200;   // [8][128]
constexpr int OF_C  = 52224;   // [8][32]
constexpr int OF_RD = 52480;   // [8][2][4]
constexpr int OF_B  = 52544;   // [128] bias slice
constexpr int SM_FLOATS = 52672;  // 210688 B
}

__global__ void __launch_bounds__(512, 1)
k_recur(const float* __restrict__ Wr, const float* __restrict__ Wp,
        const float* __restrict__ bias, const float* __restrict__ mask,
        int layer) {
    extern __shared__ float sm[];
    float* Wr_sm = sm + OF_WR;
    float* Wp_sm = sm + OF_WP;
    float* hT    = sm + OF_HT;
    float* zpart = sm + OF_ZP;
    float* z_sm  = sm + OF_Z;
    float* c_sm  = sm + OF_C;
    float* red   = sm + OF_RD;
    float* b_sm  = sm + OF_B;

    const int tid = threadIdx.x;
    const int bx = blockIdx.x;
    const int d = bx >> 6;
    const int q = bx & 63;
    const int U0 = q * 32;
    const int P0 = q * 4;
    const int widx = d * 2 + layer;

    // ---- preload weights + bias slice ----
    {
        const float* Wg = Wr + (size_t)widx * Pn * Gn;
        for (int i = tid; i < 256 * 128; i += 512) {
            int k = i >> 7, lc = i & 127;
            int gate = lc >> 5, u = lc & 31;
            Wr_sm[i] = __ldg(&Wg[(size_t)k * Gn + gate * Hn + U0 + u]);
        }
        const float* Wpg = Wp + (size_t)widx * Hn * Pn;
        for (int k = tid; k < Hn; k += 512) {
            float4 v = __ldg((const float4*)&Wpg[(size_t)k * Pn + P0]);
            Wp_sm[k] = v.x;
            Wp_sm[2048 + k] = v.y;
            Wp_sm[4096 + k] = v.z;
            Wp_sm[6144 + k] = v.w;
        }
        if (tid < 128) {
            int gate = tid >> 5, u = tid & 31;
            b_sm[tid] = __ldg(&bias[(size_t)widx * Gn + gate * Hn + U0 + u]);
        }
    }
    if (tid < 256) c_sm[tid] = 0.f;

    const unsigned base = *((volatile unsigned*)&g_flag[d]);
    unsigned target = base;
    float h_own = 0.f;
    float* __restrict__ yb = (layer == 0) ? g_y0[d] : g_y1[d];
    float* __restrict__ hg = g_h[d];
    float* __restrict__ ag = g_a[d];
    const float* __restrict__ xWd = g_xW[d];
    __syncthreads();

    // role indices (R9 mapping)
    const int kc = tid >> 5;          // phase1 (tid<256): k-chunk
    const int cg = tid & 31;          // phase1: 4-col group
    const int rb = tid >> 6;          // reduce: batch
    const int l2 = (tid & 63) * 2;    // reduce: 2 cols
    const int rgate = l2 >> 5, ru = l2 & 31;
    const int w = tid >> 5;           // phase2 warp
    const int lane = tid & 31;
    const int pb = w >> 1;            // phase2 batch
    const int half = w & 1;           // phase2 k half

    for (int s = 0; s < Tn; ++s) {
        const int t = d ? (Tn - 1 - s) : s;

        // prefetch xW for the reduce stage (hide DRAM latency behind phase1)
        float2 xwv = __ldcg((const float2*)&xWd[((size_t)s * Bn + rb) * Gn +
                                                rgate * Hn + U0 + ru]);

        // ---- stage h transposed: hT[p*8+b] = h[b*256+p] ----
        if (s == 0) {
            for (int i = tid; i < Bn * Pn; i += 512) hT[i] = 0.f;
        } else {
#pragma unroll
            for (int i = tid; i < Bn * Pn; i += 512) {
                int b = i >> 8, p = i & 255;
                hT[p * 8 + b] = __ldcg(&hg[i]);
            }
        }
        __syncthreads();

        // ---- phase 1: z partials = h @ Wr (8 k-chunks of 32, warps 0-7) ----
        if (tid < 256) {
            float acc[8][4];
#pragma unroll
            for (int b = 0; b < 8; ++b)
                acc[b][0] = acc[b][1] = acc[b][2] = acc[b][3] = 0.f;
            const float* wr0 = Wr_sm + cg * 4;
            const int ke = kc * 32 + 32;
#pragma unroll 4
            for (int k = kc * 32; k < ke; ++k) {
                float4 wv = *(const float4*)(wr0 + k * 128);
                float h8[8];
                *(float4*)(h8) = *(const float4*)(hT + k * 8);
                *(float4*)(h8 + 4) = *(const float4*)(hT + k * 8 + 4);
#pragma unroll
                for (int b = 0; b < 8; ++b) {
                    acc[b][0] += wv.x * h8[b];
                    acc[b][1] += wv.y * h8[b];
                    acc[b][2] += wv.z * h8[b];
                    acc[b][3] += wv.w * h8[b];
                }
            }
#pragma unroll
            for (int b = 0; b < 8; ++b)
                *(float4*)(zpart + kc * 1024 + b * 128 + cg * 4) =
                    make_float4(acc[b][0], acc[b][1], acc[b][2], acc[b][3]);
        }
        __syncthreads();

        // ---- reduce k-chunks + add xW + bias ----
        {
            float z0 = xwv.x + b_sm[l2];
            float z1 = xwv.y + b_sm[l2 + 1];
#pragma unroll
            for (int kk = 0; kk < 8; ++kk) {
                float2 p = *(const float2*)(zpart + kk * 1024 + rb * 128 + l2);
                z0 += p.x;
                z1 += p.y;
            }
            *(float2*)(z_sm + rb * 128 + l2) = make_float2(z0, z1);
        }
        __syncthreads();

        // ---- gates / cell / a ----
        if (tid < 256) {
            const int b2 = tid >> 5, u = tid & 31;
            float zi = z_sm[b2 * 128 + u];
            float zf = z_sm[b2 * 128 + 32 + u];
            float zg = z_sm[b2 * 128 + 64 + u];
            float zo = z_sm[b2 * 128 + 96 + u];
            float ig = fsig(zi), fg = fsig(zf), gg = ftanh(zg), og = fsig(zo);
            float cold = c_sm[tid];
            float cn = fminf(3.f, fmaxf(-3.f, fg * cold + ig * gg));
            float mt = __ldg(&mask[b2 * Tn + t]);
            c_sm[tid] = (mt > 0.f) ? cn : cold;
            __stcg(&ag[b2 * Hn + U0 + u], og * ftanh(cn));
        }
        target += DBLK;
        dir_barrier(d, target, tid);

        // ---- phase 2: h cols P0..P0+3 = clip(a @ Wp) ----
        {
            const float4* av4 = (const float4*)(ag + pb * Hn + half * 1024);
            float q0 = 0.f, q1 = 0.f, q2 = 0.f, q3 = 0.f;
#pragma unroll
            for (int j = 0; j < 8; ++j) {
                float4 av = __ldcg(av4 + lane + j * 32);
                const int kk = half * 1024 + (lane + j * 32) * 4;
                float4 wa = *(const float4*)&Wp_sm[kk];
                float4 wb = *(const float4*)&Wp_sm[2048 + kk];
                float4 wc = *(const float4*)&Wp_sm[4096 + kk];
                float4 wd = *(const float4*)&Wp_sm[6144 + kk];
                q0 += av.x * wa.x + av.y * wa.y + av.z * wa.z + av.w * wa.w;
                q1 += av.x * wb.x + av.y * wb.y + av.z * wb.z + av.w * wb.w;
                q2 += av.x * wc.x + av.y * wc.y + av.z * wc.z + av.w * wc.w;
                q3 += av.x * wd.x + av.y * wd.y + av.z * wd.z + av.w * wd.w;
            }
#pragma unroll
            for (int off = 16; off; off >>= 1) {
                q0 += __shfl_xor_sync(0xffffffffu, q0, off);
                q1 += __shfl_xor_sync(0xffffffffu, q1, off);
                q2 += __shfl_xor_sync(0xffffffffu, q2, off);
                q3 += __shfl_xor_sync(0xffffffffu, q3, off);
            }
            if (lane == 0)
                *(float4*)(red + (pb * 2 + half) * 4) = make_float4(q0, q1, q2, q3);
        }
        __syncthreads();
        if (tid < 32) {
            const int bb = tid >> 2, pp = tid & 3;
            float hv = red[(bb * 2) * 4 + pp] + red[(bb * 2 + 1) * 4 + pp];
            hv = fminf(3.f, fmaxf(-3.f, hv));
            float mt = __ldg(&mask[bb * Tn + t]);
            float hn = (mt > 0.f) ? hv : h_own;
            h_own = hn;
            __stcg(&hg[bb * Pn + P0 + pp], hn);
            const size_t yidx = ((size_t)bb * Tn + t) * Pn + P0 + pp;
            yb[yidx] = hn;
            if (layer == 0) {
                // emit bf16 split of y0 for the layer-1 xW GEMM
                __nv_bfloat16 hi = __float2bfloat16(hn);
                g_xh[d][yidx] = hi;
                g_xl[d][yidx] = __float2bfloat16(hn - __bfloat162float(hi));
            }
        }
        target += DBLK;
        dir_barrier(d, target, tid);
    }
}

// ---------------------------------------------------------------------------
// Epilogue (unchanged)
// ---------------------------------------------------------------------------
__device__ __forceinline__ float layer_val(int l, int b, int t, int ch) {
    if (l == 0) return g_emb[(size_t)(b * Tn + t) * En + (ch & 255)];
    const int dd = ch >> 8;
    const size_t idx = (size_t)(b * Tn + t) * Pn + (ch & 255);
    float v = g_y0[dd][idx];
    if (l == 2) v += g_y1[dd][idx];
    return v;
}

__global__ void k_stats(const float* __restrict__ mask) {
    const int b = blockIdx.x;
    const int l = blockIdx.y;
    __shared__ float red[256];
    const int tid = threadIdx.x;

    float nm = 0.f;
    for (int t = tid; t < Tn; t += 256) nm += mask[b * Tn + t];
    red[tid] = nm;
    __syncthreads();
    for (int st = 128; st > 0; st >>= 1) {
        if (tid < st) red[tid] += red[tid + st];
        __syncthreads();
    }
    const float num = red[0];
    __syncthreads();

    float smv = 0.f;
    for (int i = tid; i < Tn * 512; i += 256) {
        int t = i >> 9, ch = i & 511;
        smv += layer_val(l, b, t, ch) * mask[b * Tn + t];
    }
    red[tid] = smv;
    __syncthreads();
    for (int st = 128; st > 0; st >>= 1) {
        if (tid < st) red[tid] += red[tid + st];
        __syncthreads();
    }
    const float mean = red[0] / num;
    __syncthreads();

    float vs = 0.f;
    for (int i = tid; i < Tn * 512; i += 256) {
        int t = i >> 9, ch = i & 511;
        float m = mask[b * Tn + t];
        float dd = (layer_val(l, b, t, ch) * m - mean) * m;
        vs += dd * dd;
    }
    red[tid] = vs;
    __syncthreads();
    for (int st = 128; st > 0; st >>= 1) {
        if (tid < st) red[tid] += red[tid + st];
        __syncthreads();
    }
    if (tid == 0) {
        g_mean[l][b] = mean;
        g_var[l][b] = red[0] / num;
    }
}

__global__ void k_final(const float* __restrict__ elmo_w, const float* __restrict__ gamma,
                        float* __restrict__ out) {
    const int i = blockIdx.x * 256 + threadIdx.x;
    const int ch = i & 511;
    const int bt = i >> 9;
    const int b = bt / Tn;
    const int t = bt - b * Tn;
    float w0 = elmo_w[0], w1 = elmo_w[1], w2 = elmo_w[2];
    float mx = fmaxf(w0, fmaxf(w1, w2));
    float e0 = expf(w0 - mx), e1 = expf(w1 - mx), e2 = expf(w2 - mx);
    float inv = 1.f / (e0 + e1 + e2);
    float gm = gamma[0];
    float r = 0.f;
    r += e0 * inv * (layer_val(0, b, t, ch) - g_mean[0][b]) / sqrtf(g_var[0][b] + 1e-12f);
    r += e1 * inv * (layer_val(1, b, t, ch) - g_mean[1][b]) / sqrtf(g_var[1][b] + 1e-12f);
    r += e2 * inv * (layer_val(2, b, t, ch) - g_mean[2][b]) / sqrtf(g_var[2][b] + 1e-12f);
    out[i] = gm * r;
}

// ---------------------------------------------------------------------------
extern "C" void kernel_launch(void* const* d_in, const int* in_sizes, int n_in,
                              void* d_out, int out_size) {
    (void)in_sizes; (void)n_in; (void)out_size;
    const int*   tokens = (const int*)d_in[0];
    const float* mask   = (const float*)d_in[1];
    const float* table  = (const float*)d_in[2];
    const float* Wk     = (const float*)d_in[3];
    const float* Wr     = (const float*)d_in[4];
    const float* bias   = (const float*)d_in[5];
    const float* Wp     = (const float*)d_in[6];
    const float* elmo_w = (const float*)d_in[7];
    const float* gamma  = (const float*)d_in[8];
    float* out = (float*)d_out;

    const int recur_smem = SM_FLOATS * 4;  // 210688 B
    cudaFuncSetAttribute(k_recur, cudaFuncAttributeMaxDynamicSharedMemorySize,
                         recur_smem);

    k_embed<<<768, 256>>>(tokens, table);
    k_cvt_w<<<8192, 1024>>>(Wk);
    for (int layer = 0; layer < 2; ++layer) {
        k_xw_bf16<<<dim3(Gn / 128, (Tn * Bn) / 128, 2), 256>>>(layer);
        k_recur<<<NBLK, 512, recur_smem>>>(Wr, Wp, bias, mask, layer);
    }
    k_stats<<<dim3(8, 3), 256>>>(mask);
    k_final<<<1536, 256>>>(elmo_w, gamma, out);
}